// round 4
// baseline (speedup 1.0000x reference)
#include <cuda_runtime.h>

// Shapes fixed by the dataset:
// log_belief: (N=4, Cin=4, H=128, W=128)  f32
// log_kernel: (N=4, Cin=4, 100, H, W)     f32   (100 = Cout*K*K = 4*25)
// out:        (N=4, Cout=4, H, W)         f32
#define HW     16384
#define NEGBIG (-1e30f)
#define CSHIFT 12.0f

// Load the 4-wide lk window at x = 4t + j + D (j=0..3) from a row of 32 float4 quads.
// D is the tap shift (2-kx), compile-time. Neighbor-quad indices pre-clamped; lanes
// where the clamp yields garbage pair with poisoned lb values -> exp == 0.
template<int D>
__device__ __forceinline__ void lkwin(const float4* __restrict__ row,
                                      int t, int tm1, int tp1,
                                      float& r0, float& r1, float& r2, float& r3)
{
    if constexpr (D == 0) {
        float4 q = __ldcs(row + t);
        r0 = q.x; r1 = q.y; r2 = q.z; r3 = q.w;
    } else if constexpr (D == 1) {
        float4 q0 = __ldcs(row + t), q1 = __ldcs(row + tp1);
        r0 = q0.y; r1 = q0.z; r2 = q0.w; r3 = q1.x;
    } else if constexpr (D == 2) {
        float4 q0 = __ldcs(row + t), q1 = __ldcs(row + tp1);
        r0 = q0.z; r1 = q0.w; r2 = q1.x; r3 = q1.y;
    } else if constexpr (D == -1) {
        float4 qm = __ldcs(row + tm1), q0 = __ldcs(row + t);
        r0 = qm.w; r1 = q0.x; r2 = q0.y; r3 = q0.z;
    } else { // D == -2
        float4 qm = __ldcs(row + tm1), q0 = __ldcs(row + t);
        r0 = qm.z; r1 = qm.w; r2 = q0.x; r3 = q0.y;
    }
}

// Block (128 thr = 4 warps) handles one output row (n, co, yo).
// Warp j handles input channel ci = j; exp-sums are additive across ci,
// so the 4 partials combine through 2 KB of smem.
__global__ __launch_bounds__(128, 8)
void propagate_lse_v4(const float* __restrict__ lb_g,
                      const float* __restrict__ lk_g,
                      float* __restrict__ out)
{
    __shared__ float part[4][128];

    int bid = blockIdx.x;          // 0..2047 = (n, co, yo)
    int n   = bid >> 9;
    int co  = (bid >> 7) & 3;
    int yo  = bid & 127;

    int ci  = threadIdx.x >> 5;    // warp -> input channel
    int t   = threadIdx.x & 31;    // lane: owns outputs xo = 4t..4t+3

    int tm1 = (t == 0)  ? 0  : t - 1;
    int tp1 = (t == 31) ? 31 : t + 1;

    // valid ky range is contiguous: 0 <= yo+2-ky < 128
    int ky_lo = max(0, yo - 125);
    int ky_hi = min(4, yo + 2);

    float s0 = 0.f, s1 = 0.f, s2 = 0.f, s3 = 0.f;

    const float* lb_p = lb_g + (size_t)(n*4 + ci) * HW;
    const float* lk_p = lk_g + (size_t)((n*4 + ci)*100 + co*25) * HW;

    #pragma unroll 1
    for (int ky = ky_lo; ky <= ky_hi; ky++) {
        int yi = yo + 2 - ky;

        // ---- lb window: absolute x = 4t + o, o = -2..5 -> w0..w7 ----
        const float4* b4 = (const float4*)(lb_p + (size_t)yi * 128);
        float4 bm = __ldg(b4 + tm1);
        float4 bc = __ldg(b4 + t);
        float4 bp = __ldg(b4 + tp1);
        float w0 = bm.z, w1 = bm.w;
        float w2 = bc.x, w3 = bc.y, w4 = bc.z, w5 = bc.w;
        float w6 = bp.x, w7 = bp.y;
        if (t == 0)  { w0 = NEGBIG; w1 = NEGBIG; }
        if (t == 31) { w6 = NEGBIG; w7 = NEGBIG; }

        const float* plane0 = lk_p + (size_t)(ky*5) * HW + (size_t)yi * 128;

        float r0, r1, r2, r3;
        // kx = 0 (D=+2): lb offsets j+2 -> w4..w7
        lkwin<2>((const float4*)(plane0 + 0*HW), t, tm1, tp1, r0, r1, r2, r3);
        s0 += __expf(w4 + r0 + CSHIFT);
        s1 += __expf(w5 + r1 + CSHIFT);
        s2 += __expf(w6 + r2 + CSHIFT);
        s3 += __expf(w7 + r3 + CSHIFT);
        // kx = 1 (D=+1): w3..w6
        lkwin<1>((const float4*)(plane0 + 1*HW), t, tm1, tp1, r0, r1, r2, r3);
        s0 += __expf(w3 + r0 + CSHIFT);
        s1 += __expf(w4 + r1 + CSHIFT);
        s2 += __expf(w5 + r2 + CSHIFT);
        s3 += __expf(w6 + r3 + CSHIFT);
        // kx = 2 (D=0): w2..w5
        lkwin<0>((const float4*)(plane0 + 2*HW), t, tm1, tp1, r0, r1, r2, r3);
        s0 += __expf(w2 + r0 + CSHIFT);
        s1 += __expf(w3 + r1 + CSHIFT);
        s2 += __expf(w4 + r2 + CSHIFT);
        s3 += __expf(w5 + r3 + CSHIFT);
        // kx = 3 (D=-1): w1..w4
        lkwin<-1>((const float4*)(plane0 + 3*HW), t, tm1, tp1, r0, r1, r2, r3);
        s0 += __expf(w1 + r0 + CSHIFT);
        s1 += __expf(w2 + r1 + CSHIFT);
        s2 += __expf(w3 + r2 + CSHIFT);
        s3 += __expf(w4 + r3 + CSHIFT);
        // kx = 4 (D=-2): w0..w3
        lkwin<-2>((const float4*)(plane0 + 4*HW), t, tm1, tp1, r0, r1, r2, r3);
        s0 += __expf(w0 + r0 + CSHIFT);
        s1 += __expf(w1 + r1 + CSHIFT);
        s2 += __expf(w2 + r2 + CSHIFT);
        s3 += __expf(w3 + r3 + CSHIFT);
    }

    // stash per-ci partial exp-sums
    float4 sv; sv.x = s0; sv.y = s1; sv.z = s2; sv.w = s3;
    ((float4*)part[ci])[t] = sv;
    __syncthreads();

    // combine 4 ci partials; 128 threads -> one output each
    int i = threadIdx.x;
    float sum = (part[0][i] + part[1][i]) + (part[2][i] + part[3][i]);
    out[(size_t)((n*4 + co)*128 + yo) * 128 + i] = __logf(sum) - CSHIFT;
}

extern "C" void kernel_launch(void* const* d_in, const int* in_sizes, int n_in,
                              void* d_out, int out_size)
{
    const float* lb = (const float*)d_in[0];
    const float* lk = (const float*)d_in[1];
    float* out = (float*)d_out;
    // 2048 blocks: one per (n, co, yo) output row
    propagate_lse_v4<<<2048, 128>>>(lb, lk, out);
}